// round 3
// baseline (speedup 1.0000x reference)
#include <cuda_runtime.h>
#include <math.h>

#define NN 8192

// scratch (no allocations allowed)
__device__ double g_acc;
__device__ float2 g_ye[NN];     // (Y[j], exp(theta[j]))
__device__ float  g_theta[NN];

__global__ void cox_prep(const float* __restrict__ Y,
                         const float* __restrict__ logits) {
    int i = blockIdx.x * blockDim.x + threadIdx.x;
    if (i == 0) g_acc = 0.0;
    if (i < NN) {
        float t = 1.0f / (1.0f + __expf(-logits[i]));   // sigmoid
        g_theta[i] = t;
        g_ye[i] = make_float2(Y[i], __expf(t));
    }
}

// 256 blocks x 256 threads. Each block caches all (Y, e) pairs in smem.
// Each warp handles 4 rows i; lanes stride j.
__global__ void cox_main(const int* __restrict__ c) {
    extern __shared__ float2 sye[];

    for (int j = threadIdx.x; j < NN; j += blockDim.x)
        sye[j] = g_ye[j];
    __syncthreads();

    const int lane = threadIdx.x & 31;
    const int warp = threadIdx.x >> 5;
    const int gw   = blockIdx.x * (blockDim.x >> 5) + warp;  // 0..2047
    const int i0   = gw * 4;                                 // 4 rows per warp

    const float yi0 = sye[i0 + 0].x;
    const float yi1 = sye[i0 + 1].x;
    const float yi2 = sye[i0 + 2].x;
    const float yi3 = sye[i0 + 3].x;

    float p0 = 0.f, p1 = 0.f, p2 = 0.f, p3 = 0.f;

    #pragma unroll 8
    for (int j = lane; j < NN; j += 32) {
        float2 ye = sye[j];
        if (ye.x >= yi0) p0 += ye.y;
        if (ye.x >= yi1) p1 += ye.y;
        if (ye.x >= yi2) p2 += ye.y;
        if (ye.x >= yi3) p3 += ye.y;
    }

    #pragma unroll
    for (int o = 16; o; o >>= 1) {
        p0 += __shfl_xor_sync(0xffffffffu, p0, o);
        p1 += __shfl_xor_sync(0xffffffffu, p1, o);
        p2 += __shfl_xor_sync(0xffffffffu, p2, o);
        p3 += __shfl_xor_sync(0xffffffffu, p3, o);
    }

    if (lane == 0) {
        double local = 0.0;
        if (c[i0 + 0]) local += (double)(g_theta[i0 + 0] - logf(p0));
        if (c[i0 + 1]) local += (double)(g_theta[i0 + 1] - logf(p1));
        if (c[i0 + 2]) local += (double)(g_theta[i0 + 2] - logf(p2));
        if (c[i0 + 3]) local += (double)(g_theta[i0 + 3] - logf(p3));
        if (local != 0.0) atomicAdd(&g_acc, local);
    }
}

__global__ void cox_finish(float* __restrict__ out) {
    out[0] = (float)(-g_acc / (double)NN);
}

extern "C" void kernel_launch(void* const* d_in, const int* in_sizes, int n_in,
                              void* d_out, int out_size) {
    const float* Y      = (const float*)d_in[0];
    const int*   c      = (const int*)  d_in[1];
    const float* logits = (const float*)d_in[2];
    float* out = (float*)d_out;

    (void)in_sizes; (void)n_in; (void)out_size;

    const int smem = NN * sizeof(float2);  // 64 KB
    cudaFuncSetAttribute(cox_main, cudaFuncAttributeMaxDynamicSharedMemorySize, smem);

    cox_prep<<<(NN + 255) / 256, 256>>>(Y, logits);
    cox_main<<<NN / (4 * 8), 256, smem>>>(c);   // 256 blocks, 8 warps * 4 rows
    cox_finish<<<1, 1>>>(out);
}